// round 10
// baseline (speedup 1.0000x reference)
#include <cuda_runtime.h>
#include <math.h>

#define BB 128      // batch
#define NN 20000    // nodes
#define MM 10       // neighbors
#define NPB 8       // nodes per block (20000 % 8 == 0)

// Persistent scratch ([N,B] layout, 16B-aligned for float4)
__device__ __align__(128) float g_llr_t[NN * BB];            // transposed input_llr (== v0)
__device__ __align__(128) float g_check[NN * BB];            // check messages
__device__ __align__(128) float g_v[3][NN * BB];             // ring of variable-message buffers

__device__ __forceinline__ const float* src_buf(int i) {
    return (i < 0) ? g_llr_t : g_v[i];
}

// [B,N] -> [N,B] tiled transpose of input_llr.
// PDL: input tile loaded (evict-first; single-use stream) before the grid sync
// so it overlaps the previous replay's tail; the g_llr_t write (read by the
// previous replay's final var) happens only after gridDependencySynchronize.
__global__ void __launch_bounds__(1024) transpose_in_kernel(const float* __restrict__ in) {
    __shared__ float tile[32][33];
    int n0 = blockIdx.x * 32, b0 = blockIdx.y * 32;
    int tx = threadIdx.x, ty = threadIdx.y;
    float val = __ldcs(in + (size_t)(b0 + ty) * NN + (n0 + tx));  // streaming read
    cudaGridDependencySynchronize();                              // prev replay drained
    tile[ty][tx] = val;
    __syncthreads();
    g_llr_t[(size_t)(n0 + ty) * BB + (b0 + tx)] = tile[tx][ty];
}

// Check-node update: gather var msgs ([N,B] rows -> one coalesced 512B load per
// edge per warp), per-edge affine from a shared (w,b) table, sign-product via
// XOR of sign bits, min-abs via fminf/fabsf.
// PDL: preamble (index/LUT loads from harness inputs only) overlaps the
// predecessor's tail; gridDependencySynchronize gates the gather.
__global__ void __launch_bounds__(256) check_kernel(
    const int* __restrict__ cidx, const int* __restrict__ et,
    const float* __restrict__ ew, const float* __restrict__ ebp,
    const float* __restrict__ alpha_p, const float* __restrict__ beta_p,
    int src)
{
    __shared__ int    s_idx[NPB][MM];
    __shared__ float2 s_wb [NPB][MM];
    int node0 = blockIdx.x * NPB;
    int tid = threadIdx.y * 32 + threadIdx.x;
    if (tid < NPB * MM) {
        int e = et[(size_t)node0 * MM + tid];
        s_idx[tid / MM][tid % MM] = cidx[(size_t)node0 * MM + tid];
        s_wb [tid / MM][tid % MM] = make_float2(ew[e], ebp[e]);
    }
    float alpha = alpha_p[0], beta = beta_p[0];
    __syncthreads();

    cudaGridDependencySynchronize();   // predecessor grid's writes now visible

    const float* __restrict__ V = src_buf(src);
    int n = node0 + threadIdx.y;
    int lane = threadIdx.x;

    unsigned sg0 = 0u, sg1 = 0u, sg2 = 0u, sg3 = 0u;
    float mn0 = 3.0e38f, mn1 = 3.0e38f, mn2 = 3.0e38f, mn3 = 3.0e38f;

#pragma unroll
    for (int m = 0; m < MM; m++) {
        int idx  = s_idx[threadIdx.y][m];
        float2 wb = s_wb[threadIdx.y][m];
        float4 v = *reinterpret_cast<const float4*>(V + (size_t)idx * BB + lane * 4);
        float x0 = fmaf(v.x, wb.x, wb.y);
        float x1 = fmaf(v.y, wb.x, wb.y);
        float x2 = fmaf(v.z, wb.x, wb.y);
        float x3 = fmaf(v.w, wb.x, wb.y);
        sg0 ^= __float_as_uint(x0 + 1e-10f);
        sg1 ^= __float_as_uint(x1 + 1e-10f);
        sg2 ^= __float_as_uint(x2 + 1e-10f);
        sg3 ^= __float_as_uint(x3 + 1e-10f);
        mn0 = fminf(mn0, fabsf(x0));
        mn1 = fminf(mn1, fabsf(x1));
        mn2 = fminf(mn2, fabsf(x2));
        mn3 = fminf(mn3, fabsf(x3));
    }
    float4 o;
    o.x = __uint_as_float(__float_as_uint(fmaf(alpha, mn0, beta)) ^ (sg0 & 0x80000000u));
    o.y = __uint_as_float(__float_as_uint(fmaf(alpha, mn1, beta)) ^ (sg1 & 0x80000000u));
    o.z = __uint_as_float(__float_as_uint(fmaf(alpha, mn2, beta)) ^ (sg2 & 0x80000000u));
    o.w = __uint_as_float(__float_as_uint(fmaf(alpha, mn3, beta)) ^ (sg3 & 0x80000000u));
    *reinterpret_cast<float4*>(g_check + (size_t)n * BB + lane * 4) = o;
}

// Variable-node update (PDL preamble like check_kernel).
// fuse < 0: write v to g_v[outb].
// fuse >= 0: final iteration — sigmoid(v + ow*llr + ob), transposed to [B,N].
__global__ void __launch_bounds__(256) var_kernel(
    const int* __restrict__ vidx, const int* __restrict__ et,
    const float* __restrict__ ew, const float* __restrict__ ebp,
    const float* __restrict__ cw_p, const float* __restrict__ cb_p,
    const float* __restrict__ wch_p, const float* __restrict__ wres,
    int outb, int p1, int p2,
    int fuse, const float* __restrict__ ow_p, const float* __restrict__ ob_p,
    float* __restrict__ out)
{
    __shared__ int    s_idx[NPB][MM];
    __shared__ float2 s_wb [NPB][MM];
    __shared__ float  s_out[NPB][132];   // staging for fused transposed output
    int node0 = blockIdx.x * NPB;
    int tid = threadIdx.y * 32 + threadIdx.x;
    if (tid < NPB * MM) {
        int e = et[(size_t)node0 * MM + tid];
        s_idx[tid / MM][tid % MM] = vidx[(size_t)node0 * MM + tid];
        s_wb [tid / MM][tid % MM] = make_float2(ew[e], ebp[e]);
    }
    float cw = cw_p[0], cb = cb_p[0], wch = wch_p[0];
    float r0 = wres[0], r1 = wres[1];
    __syncthreads();

    cudaGridDependencySynchronize();   // wait for check_kernel's g_check

    int n = node0 + threadIdx.y;
    int lane = threadIdx.x;
    size_t off = (size_t)n * BB + lane * 4;

    float s0 = 0.f, s1 = 0.f, s2 = 0.f, s3 = 0.f, bsum = 0.f;
#pragma unroll
    for (int m = 0; m < MM; m++) {
        int idx   = s_idx[threadIdx.y][m];
        float2 wb = s_wb[threadIdx.y][m];
        float4 g = *reinterpret_cast<const float4*>(g_check + (size_t)idx * BB + lane * 4);
        s0 = fmaf(g.x, wb.x, s0);
        s1 = fmaf(g.y, wb.x, s1);
        s2 = fmaf(g.z, wb.x, s2);
        s3 = fmaf(g.w, wb.x, s3);
        bsum += wb.y;
    }

    float4 llr = *reinterpret_cast<const float4*>(g_llr_t + off);
    float v0 = fmaf(wch, llr.x, fmaf(cw, s0 + bsum, cb));
    float v1 = fmaf(wch, llr.y, fmaf(cw, s1 + bsum, cb));
    float v2 = fmaf(wch, llr.z, fmaf(cw, s2 + bsum, cb));
    float v3 = fmaf(wch, llr.w, fmaf(cw, s3 + bsum, cb));

    if (p1 > -2) {
        float4 pv = *reinterpret_cast<const float4*>(src_buf(p1) + off);
        v0 = fmaf(r0, pv.x, v0); v1 = fmaf(r0, pv.y, v1);
        v2 = fmaf(r0, pv.z, v2); v3 = fmaf(r0, pv.w, v3);
    }
    if (p2 > -2) {
        // Last read of this buffer version (it is overwritten next) — evict-first.
        float4 pv = __ldcs(reinterpret_cast<const float4*>(src_buf(p2) + off));
        v0 = fmaf(r1, pv.x, v0); v1 = fmaf(r1, pv.y, v1);
        v2 = fmaf(r1, pv.z, v2); v3 = fmaf(r1, pv.w, v3);
    }

    if (fuse < 0) {
        float4 o = {v0, v1, v2, v3};
        *reinterpret_cast<float4*>(g_v[outb] + off) = o;
    } else {
        float ow = ow_p[0], ob = ob_p[0];
        float x0 = v0 + fmaf(ow, llr.x, ob);
        float x1 = v1 + fmaf(ow, llr.y, ob);
        float x2 = v2 + fmaf(ow, llr.z, ob);
        float x3 = v3 + fmaf(ow, llr.w, ob);
        s_out[threadIdx.y][lane * 4 + 0] = 1.f / (1.f + expf(-x0));
        s_out[threadIdx.y][lane * 4 + 1] = 1.f / (1.f + expf(-x1));
        s_out[threadIdx.y][lane * 4 + 2] = 1.f / (1.f + expf(-x2));
        s_out[threadIdx.y][lane * 4 + 3] = 1.f / (1.f + expf(-x3));
        __syncthreads();
        int b = tid >> 1;
        int p = (tid & 1) * 4;
        float4 o;
        o.x = s_out[p + 0][b];
        o.y = s_out[p + 1][b];
        o.z = s_out[p + 2][b];
        o.w = s_out[p + 3][b];
        // Output is never re-read: write-through, don't pollute L2.
        __stwt(reinterpret_cast<float4*>(out + (size_t)b * NN + node0 + p), o);
    }
}

// PDL launch helper: programmatic stream serialization so this kernel's
// preamble overlaps the predecessor's tail (implicit trigger at kernel end).
template <typename... Args>
static void launch_pdl(void (*kern)(Args...), dim3 grid, dim3 block, Args... args)
{
    cudaLaunchConfig_t cfg = {};
    cfg.gridDim = grid;
    cfg.blockDim = block;
    cfg.dynamicSmemBytes = 0;
    cfg.stream = 0;
    cudaLaunchAttribute attr[1];
    attr[0].id = cudaLaunchAttributeProgrammaticStreamSerialization;
    attr[0].val.programmaticStreamSerializationAllowed = 1;
    cfg.attrs = attr;
    cfg.numAttrs = 1;
    cudaLaunchKernelEx(&cfg, kern, args...);
}

extern "C" void kernel_launch(void* const* d_in, const int* in_sizes, int n_in,
                              void* d_out, int out_size)
{
    const float* input_llr  = (const float*)d_in[0];
    const float* check_ew   = (const float*)d_in[1];
    const float* check_eb   = (const float*)d_in[2];
    const float* alpha      = (const float*)d_in[3];
    const float* beta       = (const float*)d_in[4];
    const float* var_ew     = (const float*)d_in[5];
    const float* var_eb     = (const float*)d_in[6];
    const float* combine_w  = (const float*)d_in[7];
    const float* combine_b  = (const float*)d_in[8];
    const float* w_ch       = (const float*)d_in[9];
    const float* w_res      = (const float*)d_in[10];
    const float* out_w      = (const float*)d_in[11];
    const float* out_b      = (const float*)d_in[12];
    const int*   check_index = (const int*)d_in[13];
    const int*   var_index   = (const int*)d_in[14];
    const int*   edge_type   = (const int*)d_in[15];

    dim3 tb(32, 32), tg(NN / 32, BB / 32);
    launch_pdl(transpose_in_kernel, tg, tb, input_llr);

    dim3 cb(32, NPB), cg(NN / NPB);

    // Version map: v1=buf0, v2=buf1, v3=buf2, v4=buf0 (in-place over dead v1;
    // p2 read-before-write per-thread at same offset), v5=fused output.
    // Taps lag one iteration (reference updates `prev` after the tap sum):
    // iter t produces v_{t+1} with taps p1=v_{t-1}, p2=v_{t-2}.
    const int srcs[5] = {-1, 0, 1, 2, 0};
    const int outs[5] = { 0, 1, 2, 0, -1};
    const int p1s[5]  = {-2,-1, 0, 1, 2};
    const int p2s[5]  = {-2,-2,-1, 0, 1};

    for (int it = 0; it < 5; it++) {
        launch_pdl(check_kernel, cg, cb,
                   check_index, edge_type, check_ew, check_eb,
                   alpha, beta, srcs[it]);
        int fuse = (it == 4) ? 0 : -1;
        launch_pdl(var_kernel, cg, cb,
                   var_index, edge_type, var_ew, var_eb,
                   combine_w, combine_b, w_ch, w_res,
                   outs[it], p1s[it], p2s[it],
                   fuse, out_w, out_b, (float*)d_out);
    }
}